// round 2
// baseline (speedup 1.0000x reference)
#include <cuda_runtime.h>

#define CIN 128
#define COUT 256
#define HH 64
#define WW 64
#define KTOP 64
#define NOISE_SCALE (8.0f/255.0f)
#define CHUNK 8

// scratch: transposed weights [ (ci*9+tap) ][ co ], and per-cout sum|w|
__device__ float g_wt[1152 * 256];
__device__ float g_wbias[256];

__device__ __forceinline__ unsigned long long ffma2(unsigned long long a,
                                                    unsigned long long b,
                                                    unsigned long long c) {
    unsigned long long d;
    asm("fma.rn.f32x2 %0, %1, %2, %3;" : "=l"(d) : "l"(a), "l"(b), "l"(c));
    return d;
}
__device__ __forceinline__ unsigned long long pack2(float lo, float hi) {
    unsigned long long r;
    asm("mov.b64 %0, {%1,%2};" : "=l"(r) : "f"(lo), "f"(hi));
    return r;
}
__device__ __forceinline__ void unpack2(unsigned long long v, float& lo, float& hi) {
    asm("mov.b64 {%0,%1}, %2;" : "=f"(lo), "=f"(hi) : "l"(v));
}

__global__ void prep_transpose(const float* __restrict__ w) {
    int j = blockIdx.x;        // 0..1151  (ci*9 + tap)
    int co = threadIdx.x;      // 0..255
    g_wt[j * COUT + co] = w[co * 1152 + j];
}

__global__ void prep_bias(const float* __restrict__ w) {
    __shared__ float red[128];
    int co = blockIdx.x;
    float s = 0.f;
    for (int j = threadIdx.x; j < 1152; j += 128) s += fabsf(w[co * 1152 + j]);
    red[threadIdx.x] = s;
    __syncthreads();
    for (int off = 64; off > 0; off >>= 1) {
        if (threadIdx.x < off) red[threadIdx.x] += red[threadIdx.x + off];
        __syncthreads();
    }
    if (threadIdx.x == 0) g_wbias[co] = red[0];
}

// Block: one (batch, 8x8 spatial tile). 256 threads.
// thread t: cw = t>>4 -> couts cw*16..cw*16+15 ; pq = t&15 -> positions pq*4..pq*4+3
// (position p: py = p>>3, px = p&7; a thread's 4 positions share a row)
__global__ void __launch_bounds__(256, 2)
conv_topk_kernel(const float* __restrict__ x, const float* __restrict__ rbias,
                 const float* __restrict__ noise, float* __restrict__ out) {
    extern __shared__ float smem[];
    float* w_s  = smem;                    // CHUNK*9*256 = 18432 floats
    float* o_s  = smem;                    // overlap (epilogue): 64*257 = 16448 floats
    float* in_s = smem + 18432;            // CHUNK*10*11 = 880 floats
    unsigned* tkey_s = (unsigned*)(smem + 18432 + 880);   // 64
    float* rb_s = (float*)(tkey_s + 64);                  // 256
    float* wb_s = rb_s + 256;                             // 256

    const int t  = threadIdx.x;
    const int b  = blockIdx.z;
    const int y0 = blockIdx.y * 8;
    const int x0 = blockIdx.x * 8;

    const int cw  = t >> 4;
    const int pq  = t & 15;
    const int py  = pq >> 1;
    const int px0 = (pq & 1) * 4;

    rb_s[t] = rbias[t];
    wb_s[t] = g_wbias[t];

    unsigned long long acc[32];
#pragma unroll
    for (int i = 0; i < 32; i++) acc[i] = 0ull;

    for (int c0 = 0; c0 < CIN; c0 += CHUNK) {
        __syncthreads();
        // weights: contiguous coalesced float4 copy (already transposed)
        {
            const float4* src = (const float4*)(g_wt + (size_t)c0 * 9 * COUT);
            float4* dst = (float4*)w_s;
#pragma unroll
            for (int i = 0; i < 18; i++) dst[t + i * 256] = src[t + i * 256];
        }
        // input tile with halo (zero pad at borders)
        for (int i = t; i < CHUNK * 100; i += 256) {
            int ci = i / 100;
            int rem = i - ci * 100;
            int r = rem / 10;
            int c = rem - r * 10;
            int gy = y0 - 1 + r;
            int gx = x0 - 1 + c;
            float v = 0.f;
            if ((unsigned)gy < HH && (unsigned)gx < WW)
                v = x[(((size_t)b * CIN + c0 + ci) * HH + gy) * WW + gx];
            in_s[ci * 110 + r * 11 + c] = v;
        }
        __syncthreads();
#pragma unroll
        for (int ci = 0; ci < CHUNK; ci++) {
#pragma unroll
            for (int kh = 0; kh < 3; kh++) {
                const float* row = in_s + ci * 110 + (py + kh) * 11 + px0;
                unsigned long long ip[6];
#pragma unroll
                for (int j = 0; j < 6; j++) {
                    float fv = row[j];
                    ip[j] = pack2(fv, fv);
                }
#pragma unroll
                for (int kw = 0; kw < 3; kw++) {
                    const ulonglong2* wp2 =
                        (const ulonglong2*)(w_s + ((ci * 9) + kh * 3 + kw) * COUT + cw * 16);
#pragma unroll
                    for (int q = 0; q < 4; q++) {
                        ulonglong2 wq = wp2[q];
#pragma unroll
                        for (int i = 0; i < 4; i++) {
                            acc[(q * 2 + 0) * 4 + i] = ffma2(wq.x, ip[i + kw], acc[(q * 2 + 0) * 4 + i]);
                            acc[(q * 2 + 1) * 4 + i] = ffma2(wq.y, ip[i + kw], acc[(q * 2 + 1) * 4 + i]);
                        }
                    }
                }
            }
        }
    }
    __syncthreads();   // all reads of w_s done; safe to overlay o_s

    // spill accumulators to smem [pos][co]
#pragma unroll
    for (int pr = 0; pr < 8; pr++) {
        int co = cw * 16 + (pr >> 1) * 4 + (pr & 1) * 2;
#pragma unroll
        for (int i = 0; i < 4; i++) {
            float lo, hi;
            unpack2(acc[pr * 4 + i], lo, hi);
            int pos = pq * 4 + i;
            o_s[pos * 257 + co]     = lo;
            o_s[pos * 257 + co + 1] = hi;
        }
    }
    __syncthreads();

    // coalesced noise read + inject:  v += sum|w|_co * NS * (2u - 1)
    // 64 pos * 256 co = 16384 elements -> 64 iterations of 256 threads
#pragma unroll 4
    for (int it = 0; it < 64; it++) {
        int i = it * 256 + t;
        int co = i >> 6;
        int yy = (i >> 3) & 7;
        int xx = i & 7;
        float u = noise[(((size_t)b * COUT + co) * HH + y0 + yy) * WW + x0 + xx];
        int pos = yy * 8 + xx;
        o_s[pos * 257 + co] += wb_s[co] * (NOISE_SCALE * (2.f * u - 1.f));
    }
    __syncthreads();

    // per-position exact 64th-largest via binary search on order-preserving uint keys
    {
        int wwp = t >> 5, l = t & 31;
        for (int s = 0; s < 8; s++) {
            int pos = wwp * 8 + s;
            unsigned key[8];
#pragma unroll
            for (int k = 0; k < 8; k++) {
                unsigned u = __float_as_uint(o_s[pos * 257 + l + 32 * k]);
                key[k] = (u & 0x80000000u) ? ~u : (u | 0x80000000u);
            }
            unsigned res = 0u;
            for (int bit = 31; bit >= 0; bit--) {
                unsigned cand = res | (1u << bit);
                unsigned c = 0;
#pragma unroll
                for (int k = 0; k < 8; k++) c += (key[k] >= cand) ? 1u : 0u;
                c = __reduce_add_sync(0xffffffffu, c);
                if (c >= KTOP) res = cand;   // max v with count(key>=v) >= K  == K-th largest key
            }
            if (l == 0) tkey_s[pos] = res;
        }
    }
    __syncthreads();

    // threshold (>= keeps ties, like the reference) + relu_bias + relu, coalesced store
#pragma unroll 4
    for (int it = 0; it < 64; it++) {
        int i = it * 256 + t;
        int co = i >> 6;
        int yy = (i >> 3) & 7;
        int xx = i & 7;
        int pos = yy * 8 + xx;
        float v = o_s[pos * 257 + co];
        unsigned u = __float_as_uint(v);
        unsigned kk = (u & 0x80000000u) ? ~u : (u | 0x80000000u);
        float r = (kk >= tkey_s[pos]) ? v : 0.f;
        r = fmaxf(r + rb_s[co], 0.f);
        out[(((size_t)b * COUT + co) * HH + y0 + yy) * WW + x0 + xx] = r;
    }
}

extern "C" void kernel_launch(void* const* d_in, const int* in_sizes, int n_in,
                              void* d_out, int out_size) {
    const float* x  = (const float*)d_in[0];
    const float* w  = (const float*)d_in[1];
    const float* rb = (const float*)d_in[2];
    const float* nu = (const float*)d_in[3];
    float* out = (float*)d_out;

    const int smem_bytes = (18432 + 880 + 64 + 256 + 256) * 4;  // 79552
    cudaFuncSetAttribute(conv_topk_kernel,
                         cudaFuncAttributeMaxDynamicSharedMemorySize, smem_bytes);

    prep_transpose<<<1152, 256>>>(w);
    prep_bias<<<256, 128>>>(w);
    conv_topk_kernel<<<dim3(8, 8, 32), 256, smem_bytes>>>(x, rb, nu, out);
}